// round 14
// baseline (speedup 1.0000x reference)
#include <cuda_runtime.h>
#include <cuda_fp16.h>
#include <cstdint>
#include <math.h>

// ---------------------------------------------------------------- problem dims
#define BATCH 4
#define SEQ   2048
#define DMODEL 1024
#define NROWS (BATCH * SEQ)   // 8192

// ---------------------------------------------------------------- scratch
__device__ __half g_xh  [NROWS * DMODEL];
__device__ __half g_qkv [NROWS * 3 * DMODEL];    // [8192, 3072]: q | k | v
__device__ __half g_ph  [BATCH * SEQ * SEQ];     // fp16 exp(scores)
__device__ __half g_ctxh[NROWS * DMODEL];
__device__ float  g_hid [NROWS * DMODEL];        // fp32 hidden (pre-LN)
__device__ __half g_whf [DMODEL * 3 * DMODEL];   // [1024, 3072] = Wq|Wk|Wv cols (fp16)
__device__ __half g_woh [DMODEL * DMODEL];       // Wo fp16, [V, D] row-major
__device__ float  g_rowsum[NROWS];               // softmax: per-q-row sum of exp(scores)
__device__ float  g_lnsum [NROWS];               // LN: per-row sum of hidden
__device__ float  g_lnsum2[NROWS];               // LN: per-row sum of hidden^2
__device__ unsigned g_lncnt[NROWS / 128];        // per-row-strip completion counters

// ---------------------------------------------------------------- helpers
__device__ __forceinline__ uint32_t smem_u32(const void* p) {
    uint32_t a;
    asm("{ .reg .u64 t; cvta.to.shared.u64 t, %1; cvt.u32.u64 %0, t; }" : "=r"(a) : "l"(p));
    return a;
}
__device__ __forceinline__ void cp_async16(uint32_t dst, const void* src) {
    asm volatile("cp.async.cg.shared.global [%0], [%1], 16;" :: "r"(dst), "l"(src) : "memory");
}
#define CP_COMMIT() asm volatile("cp.async.commit_group;" ::: "memory")
#define CP_WAIT1()  asm volatile("cp.async.wait_group 1;" ::: "memory")

__device__ __forceinline__ void ldsm_x4(uint32_t& r0, uint32_t& r1, uint32_t& r2, uint32_t& r3,
                                        uint32_t addr) {
    asm volatile("ldmatrix.sync.aligned.m8n8.x4.shared.b16 {%0,%1,%2,%3}, [%4];"
                 : "=r"(r0), "=r"(r1), "=r"(r2), "=r"(r3) : "r"(addr));
}
__device__ __forceinline__ void ldsm_x4_t(uint32_t& r0, uint32_t& r1, uint32_t& r2, uint32_t& r3,
                                          uint32_t addr) {
    asm volatile("ldmatrix.sync.aligned.m8n8.x4.trans.shared.b16 {%0,%1,%2,%3}, [%4];"
                 : "=r"(r0), "=r"(r1), "=r"(r2), "=r"(r3) : "r"(addr));
}
__device__ __forceinline__ void mma_f16(float* d, uint32_t a0, uint32_t a1, uint32_t a2, uint32_t a3,
                                        uint32_t b0, uint32_t b1) {
    asm volatile("mma.sync.aligned.m16n8k16.row.col.f32.f16.f16.f32 "
                 "{%0,%1,%2,%3},{%4,%5,%6,%7},{%8,%9},{%0,%1,%2,%3};"
                 : "+f"(d[0]), "+f"(d[1]), "+f"(d[2]), "+f"(d[3])
                 : "r"(a0), "r"(a1), "r"(a2), "r"(a3), "r"(b0), "r"(b1));
}

// ---------------------------------------------------------------- GEMM
// C[M,N] = alpha * A[M,K] @ op(B). A fp16 [M,K] K-major.
//  TRANSB=false: B fp16 [N,K] K-major (C = A@B^T, smem rows = n).
//  TRANSB=true : B fp16 [K,N] N-major (C = A@B, smem rows = k, ldmatrix.trans).
// Tile 128x128x64, 8 warps, warp tile 64x32, 3 stages. Compile-time geometry.
#define ROW_A   144u
#define ROW_BT  272u
#define HALF_A  18432u          // 128 * 144
#define STAGE_B 36864u
#define NSTAGE  3
#define GEMM_SMEM (NSTAGE * STAGE_B)   // 110592

// MODE: 0 = plain
//       1 = exp(alpha*acc) + atomic row sums (softmax numerator)
//       2 = scale rows by 1/rowsum (softmax denominator)
//       3 = plain fp32 out + LN stats atomics + strip counter + inline LN fixup
template<typename OT, bool TRANSB, int MODE,
         int K, int LDA, int LDB, int LDC,
         long BA, long BB, long BC, int RSTRIDE>
__global__ __launch_bounds__(256, 2)
void gemm_h_kernel(const __half* __restrict__ A, const __half* __restrict__ B,
                   OT* __restrict__ C, float alpha, float* __restrict__ rowsum,
                   float* __restrict__ rowsum2, unsigned* __restrict__ lncnt,
                   const float* __restrict__ gamma, const float* __restrict__ beta,
                   float* __restrict__ outp)
{
    extern __shared__ char smem[];
    const uint32_t sbase = smem_u32(smem);
    const int tid = threadIdx.x;
    const int wid = tid >> 5;
    const int lane = tid & 31;

    A += blockIdx.z * BA; B += blockIdx.z * BB;
    OT* Cz = C + blockIdx.z * BC;
    const int bm = blockIdx.y * 128;
    const int bn = blockIdx.x * 128;
    const __half* Ab = A + (long)bm * LDA;
    const __half* Bb = TRANSB ? (B + bn) : (B + (long)bn * LDB);

    const int wm = (wid & 1) * 64;
    const int wn = (wid >> 1) * 32;

    float acc[4][4][4];
    #pragma unroll
    for (int i = 0; i < 4; i++)
        #pragma unroll
        for (int j = 0; j < 4; j++)
            #pragma unroll
            for (int f = 0; f < 4; f++) acc[i][j][f] = 0.f;

    // ldmatrix lane components
    const uint32_t a_row = (uint32_t)(wm + (lane & 15));
    const uint32_t a_col = (uint32_t)((lane >> 4) * 16);
    const uint32_t b_row = (uint32_t)(wn + (lane & 7) + ((lane >> 4) & 1) * 8);
    const uint32_t b_col = (uint32_t)(((lane >> 3) & 1) * 16);
    const uint32_t bt_k = (uint32_t)((lane & 7) + ((lane >> 3) & 1) * 8);
    const uint32_t bt_n = (uint32_t)(wn + ((lane >> 4) & 1) * 8);

    // cp.async mappings
    const int arow0 = tid >> 3;          // 0..31
    const int ajj   = tid & 7;
    constexpr int NK = K >> 6;

    auto load_stage = [&](int s, int buf) {
        const int kt = s * 64;
        const uint32_t sa = sbase + (uint32_t)buf * STAGE_B;
        const uint32_t sb = sa + HALF_A;
        #pragma unroll
        for (int i = 0; i < 4; i++) {
            const int r = arow0 + i * 32;
            cp_async16(sa + r * ROW_A + ajj * 16u, Ab + (long)r * LDA + kt + ajj * 8);
        }
        if constexpr (!TRANSB) {
            #pragma unroll
            for (int i = 0; i < 4; i++) {
                const int r = arow0 + i * 32;
                cp_async16(sb + r * ROW_A + ajj * 16u, Bb + (long)r * LDB + kt + ajj * 8);
            }
        } else {
            #pragma unroll
            for (int i = 0; i < 4; i++) {
                const int idx = i * 256 + tid;
                const int r = idx >> 4;
                const int j = idx & 15;
                cp_async16(sb + r * ROW_BT + j * 16u, Bb + (long)(kt + r) * LDB + j * 8);
            }
        }
    };

    // prologue
    #pragma unroll
    for (int s = 0; s < 2; s++) {
        if (s < NK) load_stage(s, s);
        CP_COMMIT();
    }

    int rs = 0;
    #pragma unroll 1
    for (int it = 0; it < NK; it++) {
        CP_WAIT1();
        __syncthreads();

        const uint32_t sa = sbase + (uint32_t)rs * STAGE_B;
        const uint32_t sb = sa + HALF_A;

        #pragma unroll
        for (int ks = 0; ks < 4; ks++) {
            uint32_t a[4][4];
            #pragma unroll
            for (int mt = 0; mt < 4; mt++) {
                uint32_t addr = sa + (a_row + (uint32_t)(mt * 16)) * ROW_A
                              + a_col + (uint32_t)(ks * 32);
                ldsm_x4(a[mt][0], a[mt][1], a[mt][2], a[mt][3], addr);
            }
            uint32_t b[4][2];
            #pragma unroll
            for (int nb = 0; nb < 2; nb++) {
                uint32_t t0, t1, t2, t3;
                if constexpr (!TRANSB) {
                    uint32_t addr = sb + (b_row + (uint32_t)(nb * 16)) * ROW_A
                                  + b_col + (uint32_t)(ks * 32);
                    ldsm_x4(t0, t1, t2, t3, addr);
                } else {
                    uint32_t addr = sb + ((uint32_t)(ks * 16) + bt_k) * ROW_BT
                                  + (bt_n + (uint32_t)(nb * 16)) * 2u;
                    ldsm_x4_t(t0, t1, t2, t3, addr);
                }
                b[2 * nb][0] = t0; b[2 * nb][1] = t1;
                b[2 * nb + 1][0] = t2; b[2 * nb + 1][1] = t3;
            }
            #pragma unroll
            for (int mt = 0; mt < 4; mt++)
                #pragma unroll
                for (int nt = 0; nt < 4; nt++)
                    mma_f16(acc[mt][nt], a[mt][0], a[mt][1], a[mt][2], a[mt][3],
                            b[nt][0], b[nt][1]);

            // mid-iteration: issue next-stage gmem loads while LSU is quiet
            if (ks == 1) {
                const int sn = it + 2;
                if (sn < NK) {
                    int ws = rs + 2; if (ws >= NSTAGE) ws -= NSTAGE;
                    load_stage(sn, ws);
                }
            }
        }
        CP_COMMIT();

        if (++rs == NSTAGE) rs = 0;
    }

    // ---- epilogue ----
    const int er = lane >> 2;
    const int ec = (lane & 3) * 2;
    const int rbase = (MODE == 1 || MODE == 2) ? blockIdx.z * RSTRIDE : 0;

    #pragma unroll
    for (int mt = 0; mt < 4; mt++) {
        const int row0 = bm + wm + mt * 16 + er;
        float inv0 = 1.f, inv1 = 1.f;
        if constexpr (MODE == 2) {
            inv0 = 1.0f / rowsum[rbase + row0];
            inv1 = 1.0f / rowsum[rbase + row0 + 8];
        }
        float rsum0 = 0.f, rsum1 = 0.f;
        float rsq0 = 0.f, rsq1 = 0.f;
        #pragma unroll
        for (int nt = 0; nt < 4; nt++) {
            const int col = bn + wn + nt * 8 + ec;
            float v0 = acc[mt][nt][0] * alpha, v1 = acc[mt][nt][1] * alpha;
            float v2 = acc[mt][nt][2] * alpha, v3 = acc[mt][nt][3] * alpha;
            if constexpr (MODE == 1) {
                v0 = __expf(v0); v1 = __expf(v1);
                v2 = __expf(v2); v3 = __expf(v3);
                rsum0 += v0 + v1; rsum1 += v2 + v3;
            }
            if constexpr (MODE == 2) {
                v0 *= inv0; v1 *= inv0; v2 *= inv1; v3 *= inv1;
            }
            if constexpr (MODE == 3) {
                rsum0 += v0 + v1;           rsum1 += v2 + v3;
                rsq0  += v0 * v0 + v1 * v1; rsq1  += v2 * v2 + v3 * v3;
            }
            if constexpr (sizeof(OT) == 2) {
                *reinterpret_cast<__half2*>((__half*)Cz + (long)row0 * LDC + col) =
                    __floats2half2_rn(v0, v1);
                *reinterpret_cast<__half2*>((__half*)Cz + (long)(row0 + 8) * LDC + col) =
                    __floats2half2_rn(v2, v3);
            } else {
                *reinterpret_cast<float2*>((float*)Cz + (long)row0 * LDC + col) =
                    make_float2(v0, v1);
                *reinterpret_cast<float2*>((float*)Cz + (long)(row0 + 8) * LDC + col) =
                    make_float2(v2, v3);
            }
        }
        if constexpr (MODE == 1 || MODE == 3) {
            rsum0 += __shfl_xor_sync(0xffffffffu, rsum0, 1);
            rsum0 += __shfl_xor_sync(0xffffffffu, rsum0, 2);
            rsum1 += __shfl_xor_sync(0xffffffffu, rsum1, 1);
            rsum1 += __shfl_xor_sync(0xffffffffu, rsum1, 2);
            if constexpr (MODE == 3) {
                rsq0 += __shfl_xor_sync(0xffffffffu, rsq0, 1);
                rsq0 += __shfl_xor_sync(0xffffffffu, rsq0, 2);
                rsq1 += __shfl_xor_sync(0xffffffffu, rsq1, 1);
                rsq1 += __shfl_xor_sync(0xffffffffu, rsq1, 2);
            }
            if ((lane & 3) == 0) {
                atomicAdd(rowsum + rbase + row0, rsum0);
                atomicAdd(rowsum + rbase + row0 + 8, rsum1);
                if constexpr (MODE == 3) {
                    atomicAdd(rowsum2 + rbase + row0, rsq0);
                    atomicAdd(rowsum2 + rbase + row0 + 8, rsq1);
                }
            }
        }
    }

    // ---- MODE 3: strip-completion counter + inline LayerNorm fixup ----
    if constexpr (MODE == 3) {
        __shared__ int do_fix;
        __threadfence();                       // stats + hid stores visible
        __syncthreads();                       // all warps' atomics issued+fenced
        if (tid == 0) {
            unsigned old = atomicAdd(lncnt + blockIdx.y, 1u);
            do_fix = (old == (unsigned)(DMODEL / 128 - 1));
        }
        __syncthreads();
        if (do_fix) {
            const float4 g4 = *reinterpret_cast<const float4*>(gamma + tid * 4);
            const float4 b4 = *reinterpret_cast<const float4*>(beta + tid * 4);
            const float* hidp = (const float*)C;   // un-offset base (BC=0)
            #pragma unroll 4
            for (int r = 0; r < 128; r++) {
                const int row = bm + r;
                const float mu  = rowsum[row] * (1.0f / DMODEL);
                const float var = rowsum2[row] * (1.0f / DMODEL) - mu * mu;
                const float rstd = rsqrtf(var + 1e-5f);
                float4 h4 = *reinterpret_cast<const float4*>(hidp + (long)row * DMODEL + tid * 4);
                float4 o;
                o.x = (h4.x - mu) * rstd * g4.x + b4.x;
                o.y = (h4.y - mu) * rstd * g4.y + b4.y;
                o.z = (h4.z - mu) * rstd * g4.z + b4.z;
                o.w = (h4.w - mu) * rstd * g4.w + b4.w;
                *reinterpret_cast<float4*>(outp + (long)row * DMODEL + tid * 4) = o;
            }
        }
    }
}

// ---------------------------------------------------------------- aux kernels
// Single prep kernel: convert x -> fp16, pack/convert all weights, zero stats.
#define XN4 (NROWS * DMODEL / 4)            // 2097152
#define WN4 (4 * DMODEL * DMODEL / 4)       // 1048576

__global__ void prep_kernel(const float4* __restrict__ x,
                            const float* __restrict__ Wq, const float* __restrict__ Wk,
                            const float* __restrict__ Wv, const float* __restrict__ Wo,
                            uint2* __restrict__ xh, __half* __restrict__ whf,
                            __half* __restrict__ woh, float* __restrict__ rowsum,
                            float* __restrict__ lnsum, float* __restrict__ lnsum2,
                            unsigned* __restrict__ lncnt)
{
    const int i = blockIdx.x * blockDim.x + threadIdx.x;
    if (i < NROWS) { rowsum[i] = 0.f; lnsum[i] = 0.f; lnsum2[i] = 0.f; }
    if (i < NROWS / 128) lncnt[i] = 0u;

    const float* src;
    __half* dst;
    if (i < XN4) {
        float4 v = x[i];
        __half2 lo = __floats2half2_rn(v.x, v.y);
        __half2 hi = __floats2half2_rn(v.z, v.w);
        uint2 o;
        o.x = *reinterpret_cast<uint32_t*>(&lo);
        o.y = *reinterpret_cast<uint32_t*>(&hi);
        xh[i] = o;
        return;
    }
    const int e = (i - XN4) * 4;
    if (e < 3 * DMODEL * DMODEL) {
        const int row = e / (3 * DMODEL);
        const int col = e % (3 * DMODEL);
        const int sel = col >> 10;
        const int c   = col & 1023;
        src = (sel == 0 ? Wq : (sel == 1 ? Wk : Wv)) + (long)row * DMODEL + c;
        dst = whf + e;
    } else {
        const int e2 = e - 3 * DMODEL * DMODEL;
        src = Wo + e2;
        dst = woh + e2;
    }
    float4 v = *reinterpret_cast<const float4*>(src);
    __half2 lo = __floats2half2_rn(v.x, v.y);
    __half2 hi = __floats2half2_rn(v.z, v.w);
    uint2 o;
    o.x = *reinterpret_cast<uint32_t*>(&lo);
    o.y = *reinterpret_cast<uint32_t*>(&hi);
    *reinterpret_cast<uint2*>(dst) = o;
}

// ---------------------------------------------------------------- instantiations
#define GEMM_QKV  gemm_h_kernel<__half, true,  0, 1024, 1024, 3072, 3072, 0L, 0L, 0L, 0>
#define GEMM_SCR  gemm_h_kernel<__half, false, 1, 1024, 3072, 3072, 2048, \
                                (long)SEQ * 3 * DMODEL, (long)SEQ * 3 * DMODEL, (long)SEQ * SEQ, SEQ>
#define GEMM_CTX  gemm_h_kernel<__half, true,  2, 2048, 2048, 3072, 1024, \
                                (long)SEQ * SEQ, (long)SEQ * 3 * DMODEL, (long)SEQ * DMODEL, SEQ>
#define GEMM_OUT  gemm_h_kernel<float,  true,  3, 1024, 1024, 1024, 1024, 0L, 0L, 0L, 0>

// ---------------------------------------------------------------- launch
extern "C" void kernel_launch(void* const* d_in, const int* in_sizes, int n_in,
                              void* d_out, int out_size)
{
    const float* x     = (const float*)d_in[0];
    const float* Wq    = (const float*)d_in[1];
    const float* Wk    = (const float*)d_in[2];
    const float* Wv    = (const float*)d_in[3];
    const float* Wo    = (const float*)d_in[4];
    const float* gamma = (const float*)d_in[5];
    const float* beta  = (const float*)d_in[6];
    float* out = (float*)d_out;

    __half *xh, *qkv, *ph, *ctxh, *whf, *woh;
    float *hid, *rowsum, *lnsum, *lnsum2;
    unsigned* lncnt;
    cudaGetSymbolAddress((void**)&xh,     g_xh);
    cudaGetSymbolAddress((void**)&qkv,    g_qkv);
    cudaGetSymbolAddress((void**)&ph,     g_ph);
    cudaGetSymbolAddress((void**)&ctxh,   g_ctxh);
    cudaGetSymbolAddress((void**)&hid,    g_hid);
    cudaGetSymbolAddress((void**)&whf,    g_whf);
    cudaGetSymbolAddress((void**)&woh,    g_woh);
    cudaGetSymbolAddress((void**)&rowsum, g_rowsum);
    cudaGetSymbolAddress((void**)&lnsum,  g_lnsum);
    cudaGetSymbolAddress((void**)&lnsum2, g_lnsum2);
    cudaGetSymbolAddress((void**)&lncnt,  g_lncnt);

    cudaFuncSetAttribute((const void*)GEMM_QKV, cudaFuncAttributeMaxDynamicSharedMemorySize, GEMM_SMEM);
    cudaFuncSetAttribute((const void*)GEMM_SCR, cudaFuncAttributeMaxDynamicSharedMemorySize, GEMM_SMEM);
    cudaFuncSetAttribute((const void*)GEMM_CTX, cudaFuncAttributeMaxDynamicSharedMemorySize, GEMM_SMEM);
    cudaFuncSetAttribute((const void*)GEMM_OUT, cudaFuncAttributeMaxDynamicSharedMemorySize, GEMM_SMEM);

    const dim3 blk(256);

    // 0) single prep launch: convert x + weights, zero stats/counters
    prep_kernel<<<(XN4 + WN4 + 255) / 256, 256>>>(
        (const float4*)x, Wq, Wk, Wv, Wo, (uint2*)xh, whf, woh,
        rowsum, lnsum, lnsum2, lncnt);

    // 1) fused QKV projection
    GEMM_QKV<<<dim3(3 * DMODEL / 128, NROWS / 128, 1), blk, GEMM_SMEM>>>(
        xh, whf, qkv, 1.0f, nullptr, nullptr, nullptr, nullptr, nullptr, nullptr);

    // 2) ph = exp(q @ k^T / 32), rowsum accumulated atomically
    GEMM_SCR<<<dim3(SEQ / 128, SEQ / 128, BATCH), blk, GEMM_SMEM>>>(
        qkv, qkv + DMODEL, ph, 1.0f / 32.0f, rowsum, nullptr, nullptr, nullptr, nullptr, nullptr);

    // 3) ctx = (ph @ v) * (1/rowsum)
    GEMM_CTX<<<dim3(DMODEL / 128, SEQ / 128, BATCH), blk, GEMM_SMEM>>>(
        ph, qkv + 2 * DMODEL, ctxh, 1.0f, rowsum, nullptr, nullptr, nullptr, nullptr, nullptr);

    // 4) hidden = ctx @ woh, fused LN stats + strip-fixup LayerNorm -> out
    GEMM_OUT<<<dim3(DMODEL / 128, NROWS / 128, 1), blk, GEMM_SMEM>>>(
        ctxh, woh, hid, 1.0f, lnsum, lnsum2, lncnt, gamma, beta, out);
}

// round 16
// speedup vs baseline: 1.6360x; 1.6360x over previous
#include <cuda_runtime.h>
#include <cuda_fp16.h>
#include <cstdint>
#include <math.h>

// ---------------------------------------------------------------- problem dims
#define BATCH 4
#define SEQ   2048
#define DMODEL 1024
#define NROWS (BATCH * SEQ)   // 8192

// ---------------------------------------------------------------- scratch
__device__ __half g_xh  [NROWS * DMODEL];
__device__ __half g_qkv [NROWS * 3 * DMODEL];    // [8192, 3072]: q | k | v
__device__ __half g_ph  [BATCH * SEQ * SEQ];     // fp16 exp(scores)
__device__ __half g_ctxh[NROWS * DMODEL];
__device__ float  g_hid [NROWS * DMODEL];        // fp32 hidden (pre-LN)
__device__ __half g_whf [DMODEL * 3 * DMODEL];   // [1024, 3072] = Wq|Wk|Wv cols (fp16)
__device__ __half g_woh [DMODEL * DMODEL];       // Wo fp16, [V, D] row-major
__device__ float  g_rowsum[NROWS];               // per-q-row sum of exp(scores)

// ---------------------------------------------------------------- helpers
__device__ __forceinline__ uint32_t smem_u32(const void* p) {
    uint32_t a;
    asm("{ .reg .u64 t; cvta.to.shared.u64 t, %1; cvt.u32.u64 %0, t; }" : "=r"(a) : "l"(p));
    return a;
}
__device__ __forceinline__ void cp_async16(uint32_t dst, const void* src) {
    asm volatile("cp.async.cg.shared.global [%0], [%1], 16;" :: "r"(dst), "l"(src) : "memory");
}
#define CP_COMMIT() asm volatile("cp.async.commit_group;" ::: "memory")
#define CP_WAIT1()  asm volatile("cp.async.wait_group 1;" ::: "memory")

__device__ __forceinline__ void ldsm_x4(uint32_t& r0, uint32_t& r1, uint32_t& r2, uint32_t& r3,
                                        uint32_t addr) {
    asm volatile("ldmatrix.sync.aligned.m8n8.x4.shared.b16 {%0,%1,%2,%3}, [%4];"
                 : "=r"(r0), "=r"(r1), "=r"(r2), "=r"(r3) : "r"(addr));
}
__device__ __forceinline__ void ldsm_x4_t(uint32_t& r0, uint32_t& r1, uint32_t& r2, uint32_t& r3,
                                          uint32_t addr) {
    asm volatile("ldmatrix.sync.aligned.m8n8.x4.trans.shared.b16 {%0,%1,%2,%3}, [%4];"
                 : "=r"(r0), "=r"(r1), "=r"(r2), "=r"(r3) : "r"(addr));
}
__device__ __forceinline__ void mma_f16(float* d, uint32_t a0, uint32_t a1, uint32_t a2, uint32_t a3,
                                        uint32_t b0, uint32_t b1) {
    asm volatile("mma.sync.aligned.m16n8k16.row.col.f32.f16.f16.f32 "
                 "{%0,%1,%2,%3},{%4,%5,%6,%7},{%8,%9},{%0,%1,%2,%3};"
                 : "+f"(d[0]), "+f"(d[1]), "+f"(d[2]), "+f"(d[3])
                 : "r"(a0), "r"(a1), "r"(a2), "r"(a3), "r"(b0), "r"(b1));
}

// ---------------------------------------------------------------- GEMM
// C[M,N] = alpha * A[M,K] @ op(B). A fp16 [M,K] K-major.
//  TRANSB=false: B fp16 [N,K] K-major (C = A@B^T, smem rows = n).
//  TRANSB=true : B fp16 [K,N] N-major (C = A@B, smem rows = k, ldmatrix.trans).
// Tile 128x128x64, 8 warps, warp tile 64x32, 3 stages.
// ALL geometry is compile-time: frees registers + constant-folds addressing.
#define ROW_A   144u
#define ROW_BT  272u
#define HALF_A  18432u          // 128 * 144
#define STAGE_B 36864u
#define NSTAGE  3
#define GEMM_SMEM (NSTAGE * STAGE_B)   // 110592

// MODE: 0 = plain, 1 = exp(alpha*acc) + atomic row sums, 2 = scale rows by 1/rowsum
template<typename OT, bool TRANSB, int MODE,
         int K, int LDA, int LDB, int LDC,
         long BA, long BB, long BC, int RSTRIDE>
__global__ __launch_bounds__(256, 2)
void gemm_h_kernel(const __half* __restrict__ A, const __half* __restrict__ B,
                   OT* __restrict__ C, float alpha, float* __restrict__ rowsum)
{
    extern __shared__ char smem[];
    const uint32_t sbase = smem_u32(smem);
    const int tid = threadIdx.x;
    const int wid = tid >> 5;
    const int lane = tid & 31;

    A += blockIdx.z * BA; B += blockIdx.z * BB; C += blockIdx.z * BC;
    const int bm = blockIdx.y * 128;
    const int bn = blockIdx.x * 128;
    const __half* Ab = A + (long)bm * LDA;
    const __half* Bb = TRANSB ? (B + bn) : (B + (long)bn * LDB);

    const int wm = (wid & 1) * 64;
    const int wn = (wid >> 1) * 32;

    float acc[4][4][4];
    #pragma unroll
    for (int i = 0; i < 4; i++)
        #pragma unroll
        for (int j = 0; j < 4; j++)
            #pragma unroll
            for (int f = 0; f < 4; f++) acc[i][j][f] = 0.f;

    // ldmatrix lane components
    const uint32_t a_row = (uint32_t)(wm + (lane & 15));
    const uint32_t a_col = (uint32_t)((lane >> 4) * 16);
    const uint32_t b_row = (uint32_t)(wn + (lane & 7) + ((lane >> 4) & 1) * 8);
    const uint32_t b_col = (uint32_t)(((lane >> 3) & 1) * 16);
    const uint32_t bt_k = (uint32_t)((lane & 7) + ((lane >> 3) & 1) * 8);
    const uint32_t bt_n = (uint32_t)(wn + ((lane >> 4) & 1) * 8);

    // cp.async mappings
    const int arow0 = tid >> 3;          // 0..31
    const int ajj   = tid & 7;
    constexpr int NK = K >> 6;

    auto load_stage = [&](int s, int buf) {
        const int kt = s * 64;
        const uint32_t sa = sbase + (uint32_t)buf * STAGE_B;
        const uint32_t sb = sa + HALF_A;
        #pragma unroll
        for (int i = 0; i < 4; i++) {
            const int r = arow0 + i * 32;
            cp_async16(sa + r * ROW_A + ajj * 16u, Ab + (long)r * LDA + kt + ajj * 8);
        }
        if constexpr (!TRANSB) {
            #pragma unroll
            for (int i = 0; i < 4; i++) {
                const int r = arow0 + i * 32;
                cp_async16(sb + r * ROW_A + ajj * 16u, Bb + (long)r * LDB + kt + ajj * 8);
            }
        } else {
            #pragma unroll
            for (int i = 0; i < 4; i++) {
                const int idx = i * 256 + tid;
                const int r = idx >> 4;
                const int j = idx & 15;
                cp_async16(sb + r * ROW_BT + j * 16u, Bb + (long)(kt + r) * LDB + j * 8);
            }
        }
    };

    // prologue
    #pragma unroll
    for (int s = 0; s < 2; s++) {
        if (s < NK) load_stage(s, s);
        CP_COMMIT();
    }

    int rs = 0;
    #pragma unroll 1
    for (int it = 0; it < NK; it++) {
        CP_WAIT1();
        __syncthreads();

        const uint32_t sa = sbase + (uint32_t)rs * STAGE_B;
        const uint32_t sb = sa + HALF_A;

        #pragma unroll
        for (int ks = 0; ks < 4; ks++) {
            uint32_t a[4][4];
            #pragma unroll
            for (int mt = 0; mt < 4; mt++) {
                uint32_t addr = sa + (a_row + (uint32_t)(mt * 16)) * ROW_A
                              + a_col + (uint32_t)(ks * 32);
                ldsm_x4(a[mt][0], a[mt][1], a[mt][2], a[mt][3], addr);
            }
            uint32_t b[4][2];
            #pragma unroll
            for (int nb = 0; nb < 2; nb++) {
                uint32_t t0, t1, t2, t3;
                if constexpr (!TRANSB) {
                    uint32_t addr = sb + (b_row + (uint32_t)(nb * 16)) * ROW_A
                                  + b_col + (uint32_t)(ks * 32);
                    ldsm_x4(t0, t1, t2, t3, addr);
                } else {
                    uint32_t addr = sb + ((uint32_t)(ks * 16) + bt_k) * ROW_BT
                                  + (bt_n + (uint32_t)(nb * 16)) * 2u;
                    ldsm_x4_t(t0, t1, t2, t3, addr);
                }
                b[2 * nb][0] = t0; b[2 * nb][1] = t1;
                b[2 * nb + 1][0] = t2; b[2 * nb + 1][1] = t3;
            }
            #pragma unroll
            for (int mt = 0; mt < 4; mt++)
                #pragma unroll
                for (int nt = 0; nt < 4; nt++)
                    mma_f16(acc[mt][nt], a[mt][0], a[mt][1], a[mt][2], a[mt][3],
                            b[nt][0], b[nt][1]);

            // mid-iteration: issue next-stage gmem loads while LSU is quiet
            if (ks == 1) {
                const int sn = it + 2;
                if (sn < NK) {
                    int ws = rs + 2; if (ws >= NSTAGE) ws -= NSTAGE;
                    load_stage(sn, ws);
                }
            }
        }
        CP_COMMIT();

        if (++rs == NSTAGE) rs = 0;
    }

    // ---- epilogue ----
    const int er = lane >> 2;
    const int ec = (lane & 3) * 2;
    const int rbase = (MODE != 0) ? blockIdx.z * RSTRIDE : 0;

    #pragma unroll
    for (int mt = 0; mt < 4; mt++) {
        const int row0 = bm + wm + mt * 16 + er;
        float inv0 = 1.f, inv1 = 1.f;
        if constexpr (MODE == 2) {
            inv0 = 1.0f / rowsum[rbase + row0];
            inv1 = 1.0f / rowsum[rbase + row0 + 8];
        }
        float rsum0 = 0.f, rsum1 = 0.f;
        #pragma unroll
        for (int nt = 0; nt < 4; nt++) {
            const int col = bn + wn + nt * 8 + ec;
            float v0 = acc[mt][nt][0] * alpha, v1 = acc[mt][nt][1] * alpha;
            float v2 = acc[mt][nt][2] * alpha, v3 = acc[mt][nt][3] * alpha;
            if constexpr (MODE == 1) {
                v0 = __expf(v0); v1 = __expf(v1);
                v2 = __expf(v2); v3 = __expf(v3);
                rsum0 += v0 + v1; rsum1 += v2 + v3;
            }
            if constexpr (MODE == 2) {
                v0 *= inv0; v1 *= inv0; v2 *= inv1; v3 *= inv1;
            }
            if constexpr (sizeof(OT) == 2) {
                *reinterpret_cast<__half2*>((__half*)C + (long)row0 * LDC + col) =
                    __floats2half2_rn(v0, v1);
                *reinterpret_cast<__half2*>((__half*)C + (long)(row0 + 8) * LDC + col) =
                    __floats2half2_rn(v2, v3);
            } else {
                *reinterpret_cast<float2*>((float*)C + (long)row0 * LDC + col) =
                    make_float2(v0, v1);
                *reinterpret_cast<float2*>((float*)C + (long)(row0 + 8) * LDC + col) =
                    make_float2(v2, v3);
            }
        }
        if constexpr (MODE == 1) {
            rsum0 += __shfl_xor_sync(0xffffffffu, rsum0, 1);
            rsum0 += __shfl_xor_sync(0xffffffffu, rsum0, 2);
            rsum1 += __shfl_xor_sync(0xffffffffu, rsum1, 1);
            rsum1 += __shfl_xor_sync(0xffffffffu, rsum1, 2);
            if ((lane & 3) == 0) {
                atomicAdd(rowsum + rbase + row0, rsum0);
                atomicAdd(rowsum + rbase + row0 + 8, rsum1);
            }
        }
    }
}

// ---------------------------------------------------------------- aux kernels
// Single prep kernel: convert x -> fp16, pack/convert all weights, zero rowsum.
#define XN4 (NROWS * DMODEL / 4)            // 2097152
#define WN4 (4 * DMODEL * DMODEL / 4)       // 1048576

__global__ void prep_kernel(const float4* __restrict__ x,
                            const float* __restrict__ Wq, const float* __restrict__ Wk,
                            const float* __restrict__ Wv, const float* __restrict__ Wo,
                            uint2* __restrict__ xh, __half* __restrict__ whf,
                            __half* __restrict__ woh, float* __restrict__ rowsum)
{
    const int i = blockIdx.x * blockDim.x + threadIdx.x;
    if (i < NROWS) rowsum[i] = 0.f;

    const float* src;
    __half* dst;
    if (i < XN4) {
        float4 v = x[i];
        __half2 lo = __floats2half2_rn(v.x, v.y);
        __half2 hi = __floats2half2_rn(v.z, v.w);
        uint2 o;
        o.x = *reinterpret_cast<uint32_t*>(&lo);
        o.y = *reinterpret_cast<uint32_t*>(&hi);
        xh[i] = o;
        return;
    }
    const int e = (i - XN4) * 4;
    if (e < 3 * DMODEL * DMODEL) {
        const int row = e / (3 * DMODEL);
        const int col = e % (3 * DMODEL);
        const int sel = col >> 10;
        const int c   = col & 1023;
        src = (sel == 0 ? Wq : (sel == 1 ? Wk : Wv)) + (long)row * DMODEL + c;
        dst = whf + e;
    } else {
        const int e2 = e - 3 * DMODEL * DMODEL;
        src = Wo + e2;
        dst = woh + e2;
    }
    float4 v = *reinterpret_cast<const float4*>(src);
    __half2 lo = __floats2half2_rn(v.x, v.y);
    __half2 hi = __floats2half2_rn(v.z, v.w);
    uint2 o;
    o.x = *reinterpret_cast<uint32_t*>(&lo);
    o.y = *reinterpret_cast<uint32_t*>(&hi);
    *reinterpret_cast<uint2*>(dst) = o;
}

__global__ __launch_bounds__(256)
void layernorm_kernel(const float* __restrict__ h,
                      const float* __restrict__ gamma,
                      const float* __restrict__ beta,
                      float* __restrict__ out)
{
    __shared__ float sm[8];
    const long row = blockIdx.x;
    const int tid = threadIdx.x;
    const float* r = h + row * (long)DMODEL;

    float4 v = *reinterpret_cast<const float4*>(r + tid * 4);

    float s = v.x + v.y + v.z + v.w;
    #pragma unroll
    for (int o = 16; o; o >>= 1) s += __shfl_xor_sync(0xffffffffu, s, o);
    if ((tid & 31) == 0) sm[tid >> 5] = s;
    __syncthreads();
    if (tid == 0) {
        float ss = 0.f;
        #pragma unroll
        for (int i = 0; i < 8; i++) ss += sm[i];
        sm[0] = ss;
    }
    __syncthreads();
    const float mu = sm[0] * (1.0f / DMODEL);
    __syncthreads();

    float dx = v.x - mu, dy = v.y - mu, dz = v.z - mu, dw = v.w - mu;
    float sq = dx * dx + dy * dy + dz * dz + dw * dw;
    #pragma unroll
    for (int o = 16; o; o >>= 1) sq += __shfl_xor_sync(0xffffffffu, sq, o);
    if ((tid & 31) == 0) sm[tid >> 5] = sq;
    __syncthreads();
    if (tid == 0) {
        float ss = 0.f;
        #pragma unroll
        for (int i = 0; i < 8; i++) ss += sm[i];
        sm[0] = ss;
    }
    __syncthreads();
    const float rstd = rsqrtf(sm[0] * (1.0f / DMODEL) + 1e-5f);

    float4 g = *reinterpret_cast<const float4*>(gamma + tid * 4);
    float4 b = *reinterpret_cast<const float4*>(beta + tid * 4);
    float4 o;
    o.x = dx * rstd * g.x + b.x;
    o.y = dy * rstd * g.y + b.y;
    o.z = dz * rstd * g.z + b.z;
    o.w = dw * rstd * g.w + b.w;
    *reinterpret_cast<float4*>(out + row * (long)DMODEL + tid * 4) = o;
}

// ---------------------------------------------------------------- instantiations
// QKV: [8192,1024] @ [1024,3072] (TRANSB), ldc 3072
#define GEMM_QKV  gemm_h_kernel<__half, true,  0, 1024, 1024, 3072, 3072, 0L, 0L, 0L, 0>
// scores: q @ k^T (both in qkv, lda/ldb 3072), ldc SEQ, batched
#define GEMM_SCR  gemm_h_kernel<__half, false, 1, 1024, 3072, 3072, 2048, \
                                (long)SEQ * 3 * DMODEL, (long)SEQ * 3 * DMODEL, (long)SEQ * SEQ, SEQ>
// ctx: ph @ v (v in qkv), K=SEQ, batched
#define GEMM_CTX  gemm_h_kernel<__half, true,  2, 2048, 2048, 3072, 1024, \
                                (long)SEQ * SEQ, (long)SEQ * 3 * DMODEL, (long)SEQ * DMODEL, SEQ>
// out-proj: ctx @ Wo, fp32 out
#define GEMM_OUT  gemm_h_kernel<float,  true,  0, 1024, 1024, 1024, 1024, 0L, 0L, 0L, 0>

// ---------------------------------------------------------------- launch
extern "C" void kernel_launch(void* const* d_in, const int* in_sizes, int n_in,
                              void* d_out, int out_size)
{
    const float* x     = (const float*)d_in[0];
    const float* Wq    = (const float*)d_in[1];
    const float* Wk    = (const float*)d_in[2];
    const float* Wv    = (const float*)d_in[3];
    const float* Wo    = (const float*)d_in[4];
    const float* gamma = (const float*)d_in[5];
    const float* beta  = (const float*)d_in[6];
    float* out = (float*)d_out;

    __half *xh, *qkv, *ph, *ctxh, *whf, *woh;
    float *hid, *rowsum;
    cudaGetSymbolAddress((void**)&xh,     g_xh);
    cudaGetSymbolAddress((void**)&qkv,    g_qkv);
    cudaGetSymbolAddress((void**)&ph,     g_ph);
    cudaGetSymbolAddress((void**)&ctxh,   g_ctxh);
    cudaGetSymbolAddress((void**)&hid,    g_hid);
    cudaGetSymbolAddress((void**)&whf,    g_whf);
    cudaGetSymbolAddress((void**)&woh,    g_woh);
    cudaGetSymbolAddress((void**)&rowsum, g_rowsum);

    cudaFuncSetAttribute((const void*)GEMM_QKV, cudaFuncAttributeMaxDynamicSharedMemorySize, GEMM_SMEM);
    cudaFuncSetAttribute((const void*)GEMM_SCR, cudaFuncAttributeMaxDynamicSharedMemorySize, GEMM_SMEM);
    cudaFuncSetAttribute((const void*)GEMM_CTX, cudaFuncAttributeMaxDynamicSharedMemorySize, GEMM_SMEM);
    cudaFuncSetAttribute((const void*)GEMM_OUT, cudaFuncAttributeMaxDynamicSharedMemorySize, GEMM_SMEM);

    const dim3 blk(256);

    // 0) single prep launch: convert x + weights, zero rowsums
    prep_kernel<<<(XN4 + WN4 + 255) / 256, 256>>>(
        (const float4*)x, Wq, Wk, Wv, Wo, (uint2*)xh, whf, woh, rowsum);

    // 1) fused QKV projection
    GEMM_QKV<<<dim3(3 * DMODEL / 128, NROWS / 128, 1), blk, GEMM_SMEM>>>(
        xh, whf, qkv, 1.0f, nullptr);

    // 2) ph = exp(q @ k^T / 32), rowsum accumulated atomically
    GEMM_SCR<<<dim3(SEQ / 128, SEQ / 128, BATCH), blk, GEMM_SMEM>>>(
        qkv, qkv + DMODEL, ph, 1.0f / 32.0f, rowsum);

    // 3) ctx = (ph @ v) * (1/rowsum)
    GEMM_CTX<<<dim3(DMODEL / 128, SEQ / 128, BATCH), blk, GEMM_SMEM>>>(
        ph, qkv + 2 * DMODEL, ctxh, 1.0f, rowsum);

    // 4) hidden (fp32) = ctx @ woh
    GEMM_OUT<<<dim3(DMODEL / 128, NROWS / 128, 1), blk, GEMM_SMEM>>>(
        ctxh, woh, hid, 1.0f, nullptr);

    // 5) layernorm -> out
    layernorm_kernel<<<NROWS, blk>>>(hid, gamma, beta, out);
}

// round 17
// speedup vs baseline: 1.6496x; 1.0083x over previous
#include <cuda_runtime.h>
#include <cuda_fp16.h>
#include <cstdint>
#include <math.h>

// ---------------------------------------------------------------- problem dims
#define BATCH 4
#define SEQ   2048
#define DMODEL 1024
#define NROWS (BATCH * SEQ)   // 8192

// ---------------------------------------------------------------- scratch
__device__ __half g_xh  [NROWS * DMODEL];
__device__ __half g_qkv [NROWS * 3 * DMODEL];    // [8192, 3072]: q | k | v
__device__ __half g_ph  [BATCH * SEQ * SEQ];     // fp16 exp(scores)
__device__ __half g_ctxh[NROWS * DMODEL];
__device__ float  g_hid [NROWS * DMODEL];        // fp32 hidden (pre-LN)
__device__ __half g_whf [DMODEL * 3 * DMODEL];   // [1024, 3072] = Wq|Wk|Wv cols (fp16)
__device__ __half g_woh [DMODEL * DMODEL];       // Wo fp16, [V, D] row-major
__device__ float  g_rowsum[NROWS];               // per-q-row sum of exp(scores)

// ---------------------------------------------------------------- helpers
__device__ __forceinline__ uint32_t smem_u32(const void* p) {
    uint32_t a;
    asm("{ .reg .u64 t; cvta.to.shared.u64 t, %1; cvt.u32.u64 %0, t; }" : "=r"(a) : "l"(p));
    return a;
}
// PDL: wait for the previous grid in the stream (no-op if launched without PDL attr)
#define GRID_DEP_WAIT() asm volatile("griddepcontrol.wait;" ::: "memory")

__device__ __forceinline__ void cp_async16(uint32_t dst, const void* src) {
    asm volatile("cp.async.cg.shared.global [%0], [%1], 16;" :: "r"(dst), "l"(src) : "memory");
}
#define CP_COMMIT() asm volatile("cp.async.commit_group;" ::: "memory")
#define CP_WAIT1()  asm volatile("cp.async.wait_group 1;" ::: "memory")

__device__ __forceinline__ void ldsm_x4(uint32_t& r0, uint32_t& r1, uint32_t& r2, uint32_t& r3,
                                        uint32_t addr) {
    asm volatile("ldmatrix.sync.aligned.m8n8.x4.shared.b16 {%0,%1,%2,%3}, [%4];"
                 : "=r"(r0), "=r"(r1), "=r"(r2), "=r"(r3) : "r"(addr));
}
__device__ __forceinline__ void ldsm_x4_t(uint32_t& r0, uint32_t& r1, uint32_t& r2, uint32_t& r3,
                                          uint32_t addr) {
    asm volatile("ldmatrix.sync.aligned.m8n8.x4.trans.shared.b16 {%0,%1,%2,%3}, [%4];"
                 : "=r"(r0), "=r"(r1), "=r"(r2), "=r"(r3) : "r"(addr));
}
__device__ __forceinline__ void mma_f16(float* d, uint32_t a0, uint32_t a1, uint32_t a2, uint32_t a3,
                                        uint32_t b0, uint32_t b1) {
    asm volatile("mma.sync.aligned.m16n8k16.row.col.f32.f16.f16.f32 "
                 "{%0,%1,%2,%3},{%4,%5,%6,%7},{%8,%9},{%0,%1,%2,%3};"
                 : "+f"(d[0]), "+f"(d[1]), "+f"(d[2]), "+f"(d[3])
                 : "r"(a0), "r"(a1), "r"(a2), "r"(a3), "r"(b0), "r"(b1));
}

// ---------------------------------------------------------------- GEMM
// C[M,N] = alpha * A[M,K] @ op(B). A fp16 [M,K] K-major.
//  TRANSB=false: B fp16 [N,K] K-major (C = A@B^T, smem rows = n).
//  TRANSB=true : B fp16 [K,N] N-major (C = A@B, smem rows = k, ldmatrix.trans).
// Tile 128x128x64, 8 warps, warp tile 64x32, 3 stages. Compile-time geometry.
#define ROW_A   144u
#define ROW_BT  272u
#define HALF_A  18432u          // 128 * 144
#define STAGE_B 36864u
#define NSTAGE  3
#define GEMM_SMEM (NSTAGE * STAGE_B)   // 110592

// MODE: 0 = plain, 1 = exp(alpha*acc) + atomic row sums, 2 = scale rows by 1/rowsum
template<typename OT, bool TRANSB, int MODE,
         int K, int LDA, int LDB, int LDC,
         long BA, long BB, long BC, int RSTRIDE>
__global__ __launch_bounds__(256, 2)
void gemm_h_kernel(const __half* __restrict__ A, const __half* __restrict__ B,
                   OT* __restrict__ C, float alpha, float* __restrict__ rowsum)
{
    extern __shared__ char smem[];
    const uint32_t sbase = smem_u32(smem);
    const int tid = threadIdx.x;
    const int wid = tid >> 5;
    const int lane = tid & 31;

    A += blockIdx.z * BA; B += blockIdx.z * BB; C += blockIdx.z * BC;
    const int bm = blockIdx.y * 128;
    const int bn = blockIdx.x * 128;
    const __half* Ab = A + (long)bm * LDA;
    const __half* Bb = TRANSB ? (B + bn) : (B + (long)bn * LDB);

    const int wm = (wid & 1) * 64;
    const int wn = (wid >> 1) * 32;

    float acc[4][4][4];
    #pragma unroll
    for (int i = 0; i < 4; i++)
        #pragma unroll
        for (int j = 0; j < 4; j++)
            #pragma unroll
            for (int f = 0; f < 4; f++) acc[i][j][f] = 0.f;

    // ldmatrix lane components
    const uint32_t a_row = (uint32_t)(wm + (lane & 15));
    const uint32_t a_col = (uint32_t)((lane >> 4) * 16);
    const uint32_t b_row = (uint32_t)(wn + (lane & 7) + ((lane >> 4) & 1) * 8);
    const uint32_t b_col = (uint32_t)(((lane >> 3) & 1) * 16);
    const uint32_t bt_k = (uint32_t)((lane & 7) + ((lane >> 3) & 1) * 8);
    const uint32_t bt_n = (uint32_t)(wn + ((lane >> 4) & 1) * 8);

    // cp.async mappings
    const int arow0 = tid >> 3;          // 0..31
    const int ajj   = tid & 7;
    constexpr int NK = K >> 6;

    auto load_stage = [&](int s, int buf) {
        const int kt = s * 64;
        const uint32_t sa = sbase + (uint32_t)buf * STAGE_B;
        const uint32_t sb = sa + HALF_A;
        #pragma unroll
        for (int i = 0; i < 4; i++) {
            const int r = arow0 + i * 32;
            cp_async16(sa + r * ROW_A + ajj * 16u, Ab + (long)r * LDA + kt + ajj * 8);
        }
        if constexpr (!TRANSB) {
            #pragma unroll
            for (int i = 0; i < 4; i++) {
                const int r = arow0 + i * 32;
                cp_async16(sb + r * ROW_A + ajj * 16u, Bb + (long)r * LDB + kt + ajj * 8);
            }
        } else {
            #pragma unroll
            for (int i = 0; i < 4; i++) {
                const int idx = i * 256 + tid;
                const int r = idx >> 4;
                const int j = idx & 15;
                cp_async16(sb + r * ROW_BT + j * 16u, Bb + (long)(kt + r) * LDB + j * 8);
            }
        }
    };

    // PDL: producer grid must be complete (and visible) before first gmem read
    GRID_DEP_WAIT();

    // prologue
    #pragma unroll
    for (int s = 0; s < 2; s++) {
        if (s < NK) load_stage(s, s);
        CP_COMMIT();
    }

    int rs = 0;
    #pragma unroll 1
    for (int it = 0; it < NK; it++) {
        CP_WAIT1();
        __syncthreads();

        const uint32_t sa = sbase + (uint32_t)rs * STAGE_B;
        const uint32_t sb = sa + HALF_A;

        #pragma unroll
        for (int ks = 0; ks < 4; ks++) {
            uint32_t a[4][4];
            #pragma unroll
            for (int mt = 0; mt < 4; mt++) {
                uint32_t addr = sa + (a_row + (uint32_t)(mt * 16)) * ROW_A
                              + a_col + (uint32_t)(ks * 32);
                ldsm_x4(a[mt][0], a[mt][1], a[mt][2], a[mt][3], addr);
            }
            uint32_t b[4][2];
            #pragma unroll
            for (int nb = 0; nb < 2; nb++) {
                uint32_t t0, t1, t2, t3;
                if constexpr (!TRANSB) {
                    uint32_t addr = sb + (b_row + (uint32_t)(nb * 16)) * ROW_A
                                  + b_col + (uint32_t)(ks * 32);
                    ldsm_x4(t0, t1, t2, t3, addr);
                } else {
                    uint32_t addr = sb + ((uint32_t)(ks * 16) + bt_k) * ROW_BT
                                  + (bt_n + (uint32_t)(nb * 16)) * 2u;
                    ldsm_x4_t(t0, t1, t2, t3, addr);
                }
                b[2 * nb][0] = t0; b[2 * nb][1] = t1;
                b[2 * nb + 1][0] = t2; b[2 * nb + 1][1] = t3;
            }
            #pragma unroll
            for (int mt = 0; mt < 4; mt++)
                #pragma unroll
                for (int nt = 0; nt < 4; nt++)
                    mma_f16(acc[mt][nt], a[mt][0], a[mt][1], a[mt][2], a[mt][3],
                            b[nt][0], b[nt][1]);

            // mid-iteration: issue next-stage gmem loads while LSU is quiet
            if (ks == 1) {
                const int sn = it + 2;
                if (sn < NK) {
                    int ws = rs + 2; if (ws >= NSTAGE) ws -= NSTAGE;
                    load_stage(sn, ws);
                }
            }
        }
        CP_COMMIT();

        if (++rs == NSTAGE) rs = 0;
    }

    // ---- epilogue ----
    const int er = lane >> 2;
    const int ec = (lane & 3) * 2;
    const int rbase = (MODE != 0) ? blockIdx.z * RSTRIDE : 0;

    #pragma unroll
    for (int mt = 0; mt < 4; mt++) {
        const int row0 = bm + wm + mt * 16 + er;
        float inv0 = 1.f, inv1 = 1.f;
        if constexpr (MODE == 2) {
            inv0 = 1.0f / rowsum[rbase + row0];
            inv1 = 1.0f / rowsum[rbase + row0 + 8];
        }
        float rsum0 = 0.f, rsum1 = 0.f;
        #pragma unroll
        for (int nt = 0; nt < 4; nt++) {
            const int col = bn + wn + nt * 8 + ec;
            float v0 = acc[mt][nt][0] * alpha, v1 = acc[mt][nt][1] * alpha;
            float v2 = acc[mt][nt][2] * alpha, v3 = acc[mt][nt][3] * alpha;
            if constexpr (MODE == 1) {
                v0 = __expf(v0); v1 = __expf(v1);
                v2 = __expf(v2); v3 = __expf(v3);
                rsum0 += v0 + v1; rsum1 += v2 + v3;
            }
            if constexpr (MODE == 2) {
                v0 *= inv0; v1 *= inv0; v2 *= inv1; v3 *= inv1;
            }
            if constexpr (sizeof(OT) == 2) {
                *reinterpret_cast<__half2*>((__half*)C + (long)row0 * LDC + col) =
                    __floats2half2_rn(v0, v1);
                *reinterpret_cast<__half2*>((__half*)C + (long)(row0 + 8) * LDC + col) =
                    __floats2half2_rn(v2, v3);
            } else {
                *reinterpret_cast<float2*>((float*)C + (long)row0 * LDC + col) =
                    make_float2(v0, v1);
                *reinterpret_cast<float2*>((float*)C + (long)(row0 + 8) * LDC + col) =
                    make_float2(v2, v3);
            }
        }
        if constexpr (MODE == 1) {
            rsum0 += __shfl_xor_sync(0xffffffffu, rsum0, 1);
            rsum0 += __shfl_xor_sync(0xffffffffu, rsum0, 2);
            rsum1 += __shfl_xor_sync(0xffffffffu, rsum1, 1);
            rsum1 += __shfl_xor_sync(0xffffffffu, rsum1, 2);
            if ((lane & 3) == 0) {
                atomicAdd(rowsum + rbase + row0, rsum0);
                atomicAdd(rowsum + rbase + row0 + 8, rsum1);
            }
        }
    }
}

// ---------------------------------------------------------------- aux kernels
// Single prep kernel: convert x -> fp16, pack/convert all weights, zero rowsum.
#define XN4 (NROWS * DMODEL / 4)            // 2097152
#define WN4 (4 * DMODEL * DMODEL / 4)       // 1048576

__global__ void prep_kernel(const float4* __restrict__ x,
                            const float* __restrict__ Wq, const float* __restrict__ Wk,
                            const float* __restrict__ Wv, const float* __restrict__ Wo,
                            uint2* __restrict__ xh, __half* __restrict__ whf,
                            __half* __restrict__ woh, float* __restrict__ rowsum)
{
    const int i = blockIdx.x * blockDim.x + threadIdx.x;
    if (i < NROWS) rowsum[i] = 0.f;

    const float* src;
    __half* dst;
    if (i < XN4) {
        float4 v = x[i];
        __half2 lo = __floats2half2_rn(v.x, v.y);
        __half2 hi = __floats2half2_rn(v.z, v.w);
        uint2 o;
        o.x = *reinterpret_cast<uint32_t*>(&lo);
        o.y = *reinterpret_cast<uint32_t*>(&hi);
        xh[i] = o;
        return;
    }
    const int e = (i - XN4) * 4;
    if (e < 3 * DMODEL * DMODEL) {
        const int row = e / (3 * DMODEL);
        const int col = e % (3 * DMODEL);
        const int sel = col >> 10;
        const int c   = col & 1023;
        src = (sel == 0 ? Wq : (sel == 1 ? Wk : Wv)) + (long)row * DMODEL + c;
        dst = whf + e;
    } else {
        const int e2 = e - 3 * DMODEL * DMODEL;
        src = Wo + e2;
        dst = woh + e2;
    }
    float4 v = *reinterpret_cast<const float4*>(src);
    __half2 lo = __floats2half2_rn(v.x, v.y);
    __half2 hi = __floats2half2_rn(v.z, v.w);
    uint2 o;
    o.x = *reinterpret_cast<uint32_t*>(&lo);
    o.y = *reinterpret_cast<uint32_t*>(&hi);
    *reinterpret_cast<uint2*>(dst) = o;
}

__global__ __launch_bounds__(256)
void layernorm_kernel(const float* __restrict__ h,
                      const float* __restrict__ gamma,
                      const float* __restrict__ beta,
                      float* __restrict__ out)
{
    __shared__ float sm[8];
    const long row = blockIdx.x;
    const int tid = threadIdx.x;
    const float* r = h + row * (long)DMODEL;

    GRID_DEP_WAIT();

    float4 v = *reinterpret_cast<const float4*>(r + tid * 4);

    float s = v.x + v.y + v.z + v.w;
    #pragma unroll
    for (int o = 16; o; o >>= 1) s += __shfl_xor_sync(0xffffffffu, s, o);
    if ((tid & 31) == 0) sm[tid >> 5] = s;
    __syncthreads();
    if (tid == 0) {
        float ss = 0.f;
        #pragma unroll
        for (int i = 0; i < 8; i++) ss += sm[i];
        sm[0] = ss;
    }
    __syncthreads();
    const float mu = sm[0] * (1.0f / DMODEL);
    __syncthreads();

    float dx = v.x - mu, dy = v.y - mu, dz = v.z - mu, dw = v.w - mu;
    float sq = dx * dx + dy * dy + dz * dz + dw * dw;
    #pragma unroll
    for (int o = 16; o; o >>= 1) sq += __shfl_xor_sync(0xffffffffu, sq, o);
    if ((tid & 31) == 0) sm[tid >> 5] = sq;
    __syncthreads();
    if (tid == 0) {
        float ss = 0.f;
        #pragma unroll
        for (int i = 0; i < 8; i++) ss += sm[i];
        sm[0] = ss;
    }
    __syncthreads();
    const float rstd = rsqrtf(sm[0] * (1.0f / DMODEL) + 1e-5f);

    float4 g = *reinterpret_cast<const float4*>(gamma + tid * 4);
    float4 b = *reinterpret_cast<const float4*>(beta + tid * 4);
    float4 o;
    o.x = dx * rstd * g.x + b.x;
    o.y = dy * rstd * g.y + b.y;
    o.z = dz * rstd * g.z + b.z;
    o.w = dw * rstd * g.w + b.w;
    *reinterpret_cast<float4*>(out + row * (long)DMODEL + tid * 4) = o;
}

// ---------------------------------------------------------------- instantiations
#define GEMM_QKV  gemm_h_kernel<__half, true,  0, 1024, 1024, 3072, 3072, 0L, 0L, 0L, 0>
#define GEMM_SCR  gemm_h_kernel<__half, false, 1, 1024, 3072, 3072, 2048, \
                                (long)SEQ * 3 * DMODEL, (long)SEQ * 3 * DMODEL, (long)SEQ * SEQ, SEQ>
#define GEMM_CTX  gemm_h_kernel<__half, true,  2, 2048, 2048, 3072, 1024, \
                                (long)SEQ * SEQ, (long)SEQ * 3 * DMODEL, (long)SEQ * DMODEL, SEQ>
#define GEMM_OUT  gemm_h_kernel<float,  true,  0, 1024, 1024, 1024, 1024, 0L, 0L, 0L, 0>

// PDL launch helper: launches on the null stream (same as <<<>>>) with the
// programmatic-stream-serialization attribute so this kernel may be scheduled
// while the previous grid drains; griddepcontrol.wait inside provides ordering.
static void launch_pdl(const void* func, dim3 grid, dim3 blk, size_t smem, void** args)
{
    cudaLaunchConfig_t cfg = {};
    cfg.gridDim = grid;
    cfg.blockDim = blk;
    cfg.dynamicSmemBytes = smem;
    cfg.stream = 0;
    cudaLaunchAttribute attr[1];
    attr[0].id = cudaLaunchAttributeProgrammaticStreamSerialization;
    attr[0].val.programmaticStreamSerializationAllowed = 1;
    cfg.attrs = attr;
    cfg.numAttrs = 1;
    cudaLaunchKernelExC(&cfg, func, args);
}

// ---------------------------------------------------------------- launch
extern "C" void kernel_launch(void* const* d_in, const int* in_sizes, int n_in,
                              void* d_out, int out_size)
{
    const float* x     = (const float*)d_in[0];
    const float* Wq    = (const float*)d_in[1];
    const float* Wk    = (const float*)d_in[2];
    const float* Wv    = (const float*)d_in[3];
    const float* Wo    = (const float*)d_in[4];
    const float* gamma = (const float*)d_in[5];
    const float* beta  = (const float*)d_in[6];
    float* out = (float*)d_out;

    __half *xh, *qkv, *ph, *ctxh, *whf, *woh;
    float *hid, *rowsum;
    cudaGetSymbolAddress((void**)&xh,     g_xh);
    cudaGetSymbolAddress((void**)&qkv,    g_qkv);
    cudaGetSymbolAddress((void**)&ph,     g_ph);
    cudaGetSymbolAddress((void**)&ctxh,   g_ctxh);
    cudaGetSymbolAddress((void**)&hid,    g_hid);
    cudaGetSymbolAddress((void**)&whf,    g_whf);
    cudaGetSymbolAddress((void**)&woh,    g_woh);
    cudaGetSymbolAddress((void**)&rowsum, g_rowsum);

    cudaFuncSetAttribute((const void*)GEMM_QKV, cudaFuncAttributeMaxDynamicSharedMemorySize, GEMM_SMEM);
    cudaFuncSetAttribute((const void*)GEMM_SCR, cudaFuncAttributeMaxDynamicSharedMemorySize, GEMM_SMEM);
    cudaFuncSetAttribute((const void*)GEMM_CTX, cudaFuncAttributeMaxDynamicSharedMemorySize, GEMM_SMEM);
    cudaFuncSetAttribute((const void*)GEMM_OUT, cudaFuncAttributeMaxDynamicSharedMemorySize, GEMM_SMEM);

    const dim3 blk(256);

    // 0) single prep launch (no PDL: first in chain): convert x + weights, zero rowsums
    prep_kernel<<<(XN4 + WN4 + 255) / 256, 256>>>(
        (const float4*)x, Wq, Wk, Wv, Wo, (uint2*)xh, whf, woh, rowsum);

    float one = 1.0f;
    float inv32 = 1.0f / 32.0f;
    float* nullf = nullptr;

    // 1) fused QKV projection
    {
        const __half* a = xh; const __half* b = whf; __half* c = qkv;
        void* args[] = { &a, &b, &c, &one, &nullf };
        launch_pdl((const void*)GEMM_QKV, dim3(3 * DMODEL / 128, NROWS / 128, 1), blk, GEMM_SMEM, args);
    }

    // 2) ph = exp(q @ k^T / 32), rowsum accumulated atomically
    {
        const __half* a = qkv; const __half* b = qkv + DMODEL; __half* c = ph;
        void* args[] = { &a, &b, &c, &inv32, &rowsum };
        launch_pdl((const void*)GEMM_SCR, dim3(SEQ / 128, SEQ / 128, BATCH), blk, GEMM_SMEM, args);
    }

    // 3) ctx = (ph @ v) * (1/rowsum)
    {
        const __half* a = ph; const __half* b = qkv + 2 * DMODEL; __half* c = ctxh;
        void* args[] = { &a, &b, &c, &one, &rowsum };
        launch_pdl((const void*)GEMM_CTX, dim3(DMODEL / 128, SEQ / 128, BATCH), blk, GEMM_SMEM, args);
    }

    // 4) hidden (fp32) = ctx @ woh
    {
        const __half* a = ctxh; const __half* b = woh; float* c = hid;
        void* args[] = { &a, &b, &c, &one, &nullf };
        launch_pdl((const void*)GEMM_OUT, dim3(DMODEL / 128, NROWS / 128, 1), blk, GEMM_SMEM, args);
    }

    // 5) layernorm -> out
    {
        const float* h = hid;
        void* args[] = { &h, &gamma, &beta, &out };
        launch_pdl((const void*)layernorm_kernel, dim3(NROWS), blk, 0, args);
    }
}